// round 10
// baseline (speedup 1.0000x reference)
#include <cuda_runtime.h>

#define SB 2048
#define TB 64
#define NB 256
#define NBLK 128   // blocks; 2 chains per block

typedef unsigned long long ull;

__device__ float g_part[NB];
__device__ unsigned int g_cnt;   // zero-init; reset by last block each run

static __device__ __forceinline__ ull pk2(float a, float b) {
    ull r; asm("mov.b64 %0,{%1,%2};" : "=l"(r) : "f"(a), "f"(b)); return r;
}
static __device__ __forceinline__ void upk2(ull v, float& a, float& b) {
    asm("mov.b64 {%0,%1},%2;" : "=f"(a), "=f"(b) : "l"(v));
}
static __device__ __forceinline__ ull fma2(ull a, ull b, ull c) {
    ull d; asm("fma.rn.f32x2 %0,%1,%2,%3;" : "=l"(d) : "l"(a), "l"(b), "l"(c)); return d;
}
static __device__ __forceinline__ ull add2(ull a, ull b) {
    ull d; asm("add.rn.f32x2 %0,%1,%2;" : "=l"(d) : "l"(a), "l"(b)); return d;
}
static __device__ __forceinline__ void barx(int id) {
    asm volatile("bar.sync %0, 64;" :: "r"(id) : "memory");
}

__global__ __launch_bounds__(128, 1) void crf_fused_kernel(
    const float* __restrict__ emis,     // (B, S, T)
    const float* __restrict__ startT,   // (T)
    const float* __restrict__ endT,     // (T)
    const float* __restrict__ trans,    // (T, T)
    const int*   __restrict__ tags,     // (B, S)
    const int*   __restrict__ maskp,    // (B, S)
    float*       __restrict__ out)
{
    const int tid   = threadIdx.x;
    const int w     = tid >> 5;
    const int lane  = tid & 31;
    const int g     = w & 1;                 // chain within block -> SMSPs {g, g+2}
    const int jh    = w >> 1;                // which half of the state vector
    const int j     = (jh << 5) | lane;      // owned next-state 0..63
    const int b     = blockIdx.x * 2 + g;
    const int barid = g + 1;

    const float* __restrict__ em = emis + (size_t)b * SB * TB;
    const int*   __restrict__ tg = tags  + b * SB;
    const int*   __restrict__ mk = maskp + b * SB;

    __shared__ __align__(16) float p[2][2][TB];  // [chain][parity][state]
    __shared__ float craw[2][2];                 // [chain][parity] normalizer seed
    __shared__ float nred[2][2];                 // numerator partial per (chain, warp-half)
    __shared__ int   mred[2][2];
    __shared__ float red[2][2];
    __shared__ float sred[4];
    __shared__ int   lastflag;

    // ---------------- numerator: gold tag path (64-way parallel per chain) ----------
    float nacc = 0.f;
    int   macc = 0;
    for (int t = j; t < SB; t += TB) {
        int m = mk[t];
        macc += m;
        if (t > 0 && m) {
            int tp = tg[t - 1], tc = tg[t];
            nacc += trans[tp * TB + tc] + em[t * TB + tc];
        }
    }
    if (j == 0) nacc += startT[tg[0]] + em[tg[0]];
    #pragma unroll
    for (int o = 16; o; o >>= 1) {
        nacc += __shfl_down_sync(0xffffffffu, nacc, o);
        macc += __shfl_down_sync(0xffffffffu, macc, o);
    }
    if (lane == 0) { nred[g][jh] = nacc; mred[g][jh] = macc; }

    // ---------------- E = exp(transitions) column j into registers -----------------
    ull Ecol[TB / 2];
    #pragma unroll
    for (int i = 0; i < TB / 2; i++) {
        float e0 = expf(trans[(2 * i) * TB + j]);
        float e1 = expf(trans[(2 * i + 1) * TB + j]);
        Ecol[i] = pk2(e0, e1);
    }

    // ---------------- init: p = exp(alpha0), M = 0 ---------------------------------
    float pq = __expf(startT[j] + em[j]);
    p[g][0][j] = pq;
    if (j == 0) craw[g][0] = 1.0f;

    // prefetch ring (distance 4): exp(emission) precomputed off critical path
    float eemr[4];
    int   mkr[4];
    #pragma unroll
    for (int k = 0; k < 4; k++) {
        int t = 1 + k;
        eemr[k] = (t < SB) ? __expf(em[t * TB + j]) : 1.f;
        mkr[k]  = (t < SB) ? mk[t] : 0;
    }

    double Mtot = 0.0;   // running log-offset (side chain, one DADD per step)

    // ---------------- forward recursion: one named barrier per step ----------------
    #pragma unroll 1
    for (int tb = 1; tb < SB; tb += 4) {
        #pragma unroll
        for (int k = 0; k < 4; k++) {
            const int t = tb + k;
            if (t >= SB) break;
            const int rb = k & 1;       // read parity ((t-1)&1 since tb is odd)
            const int wb = rb ^ 1;

            barx(barid);

            // normalizer path — fully hidden under the dot
            float cr  = craw[g][rb];
            float inv = __fdividef(1.0f, cr);          // rcp.approx
            float wpre = eemr[k] * inv;

            // dot: s_j = sum_i p[i] * E[i][j]  (16x LDS.128 broadcast, 32x FFMA2)
            const ulonglong2* __restrict__ pv = (const ulonglong2*)p[g][rb];
            ull a0 = 0ull, a1 = 0ull, a2 = 0ull, a3 = 0ull;
            #pragma unroll
            for (int i = 0; i < 16; i += 4) {
                ulonglong2 v0 = pv[i + 0];
                a0 = fma2(v0.x, Ecol[2 * i + 0], a0);
                a1 = fma2(v0.y, Ecol[2 * i + 1], a1);
                ulonglong2 v1 = pv[i + 1];
                a2 = fma2(v1.x, Ecol[2 * i + 2], a2);
                a3 = fma2(v1.y, Ecol[2 * i + 3], a3);
                ulonglong2 v2 = pv[i + 2];
                a0 = fma2(v2.x, Ecol[2 * i + 4], a0);
                a1 = fma2(v2.y, Ecol[2 * i + 5], a1);
                ulonglong2 v3 = pv[i + 3];
                a2 = fma2(v3.x, Ecol[2 * i + 6], a2);
                a3 = fma2(v3.y, Ecol[2 * i + 7], a3);
            }
            ull sa = add2(add2(a0, a1), add2(a2, a3));
            float s0, s1; upk2(sa, s0, s1);
            float s = s0 + s1;

            float q = mkr[k] ? s * wpre : pq;   // alpha' = M + log(cr) + log q (masked)
            pq = q;
            p[g][wb][j] = q;
            if (j == 0) craw[g][wb] = s;
            if (mkr[k]) Mtot += (double)__logf(cr);   // side chain

            // prefetch t+4
            if (t + 4 < SB) {
                eemr[k] = __expf(em[(t + 4) * TB + j]);
                mkr[k]  = mk[t + 4];
            }
        }
    }

    // ---------------- finish: den = M + log(sum_j p_j * exp(endT_j)) ---------------
    barx(barid);
    float term = p[g][1][j] * __expf(endT[j]);   // final parity after t=2047 is 1
    #pragma unroll
    for (int o = 16; o; o >>= 1)
        term += __shfl_down_sync(0xffffffffu, term, o);
    if (lane == 0) red[g][jh] = term;
    barx(barid);

    if (j == 0) {
        float total = red[g][0] + red[g][1];
        float den = (float)(Mtot + (double)logf(total));
        float num = nred[g][0] + nred[g][1];
        int   se  = mred[g][0] + mred[g][1] - 1;
        num += endT[tg[se]];
        g_part[b] = den - num;
    }

    // ---------------- fused grid reduction: last block computes the mean -----------
    __syncthreads();
    if (tid == 0) {
        __threadfence();
        unsigned int old = atomicAdd(&g_cnt, 1u);
        lastflag = (old == NBLK - 1);
    }
    __syncthreads();
    if (lastflag) {
        __threadfence();
        float v = g_part[tid] + g_part[tid + NBLK];
        #pragma unroll
        for (int o = 16; o; o >>= 1)
            v += __shfl_down_sync(0xffffffffu, v, o);
        if (lane == 0) sred[w] = v;
        __syncthreads();
        if (tid == 0) {
            float ssum = sred[0] + sred[1] + sred[2] + sred[3];
            out[0] = ssum / (float)NB;   // mean(den - num) = -(mean(num - den))
            g_cnt = 0;                    // reset for next replay
        }
    }
}

extern "C" void kernel_launch(void* const* d_in, const int* in_sizes, int n_in,
                              void* d_out, int out_size) {
    const float* emissions = (const float*)d_in[0];
    const float* startT    = (const float*)d_in[1];
    const float* endT      = (const float*)d_in[2];
    const float* trans     = (const float*)d_in[3];
    const int*   tags      = (const int*)d_in[4];
    const int*   mask      = (const int*)d_in[5];
    (void)in_sizes; (void)n_in; (void)out_size;

    crf_fused_kernel<<<NBLK, 128>>>(emissions, startT, endT, trans, tags, mask,
                                    (float*)d_out);
}